// round 15
// baseline (speedup 1.0000x reference)
#include <cuda_runtime.h>
#include <cuda_fp16.h>
#include <cstdint>
#include <math.h>

// Sliding-window causal GQA attention via mma.sync (HMMA), fp16 operands.
// B=2, S=2048, 8 kv heads x 4 q-heads/kv, D=64, WINDOW=128, fp32 in/out.
// CTA = (b, kvh, 32 queries): M=128 rows (32q x 4h), exact 160-key window,
// 8 warps, 2 CTAs/SM (40KB smem).
// Software-pipelined chunks: QK(c+1) interleaved with exp+PV(c) via
// double-buffered score fragments (chunks are data-independent), fully
// unrolled so chunk constants fold. Shuffle-free softmax: p = 2^s (offset-
// invariant, fp16-safe range), ex2.approx.f16x2; row-sum via ones-column MMA.

namespace {

constexpr int SEQ = 2048;
constexpr float SSCALE = 0.125f * 1.4426950408889634f;  // 1/sqrt(64) * log2(e)
constexpr uint32_t ONES2 = 0x3C003C00u;                  // half2(1, 1)

constexpr int SM_KH = 0;           // 160 x 128B
constexpr int SM_VH = 20480;
constexpr int SMEM_BYTES = 40960;  // 40 KB -> 2 CTAs/SM

__device__ __forceinline__ uint32_t smem_u32(const void* p) {
    uint32_t a;
    asm("{ .reg .u64 t; cvta.to.shared.u64 t, %1; cvt.u32.u64 %0, t; }" : "=r"(a) : "l"(p));
    return a;
}
__device__ __forceinline__ void ldsm4(uint32_t r[4], uint32_t a) {
    asm volatile("ldmatrix.sync.aligned.m8n8.x4.shared.b16 {%0,%1,%2,%3}, [%4];"
                 : "=r"(r[0]), "=r"(r[1]), "=r"(r[2]), "=r"(r[3]) : "r"(a));
}
__device__ __forceinline__ void ldsm4t(uint32_t r[4], uint32_t a) {
    asm volatile("ldmatrix.sync.aligned.m8n8.x4.trans.shared.b16 {%0,%1,%2,%3}, [%4];"
                 : "=r"(r[0]), "=r"(r[1]), "=r"(r[2]), "=r"(r[3]) : "r"(a));
}
__device__ __forceinline__ void mma16816(float d[4], const uint32_t a[4],
                                         uint32_t b0, uint32_t b1) {
    asm("mma.sync.aligned.m16n8k16.row.col.f32.f16.f16.f32 "
        "{%0,%1,%2,%3}, {%4,%5,%6,%7}, {%8,%9}, {%0,%1,%2,%3};"
        : "+f"(d[0]), "+f"(d[1]), "+f"(d[2]), "+f"(d[3])
        : "r"(a[0]), "r"(a[1]), "r"(a[2]), "r"(a[3]), "r"(b0), "r"(b1));
}
__device__ __forceinline__ uint32_t cvt2h(float lo, float hi) {
    uint32_t r; asm("cvt.rn.f16x2.f32 %0, %2, %1;" : "=r"(r) : "f"(lo), "f"(hi));
    return r;
}
__device__ __forceinline__ uint32_t ex2h2(uint32_t x) {
    uint32_t r; asm("ex2.approx.f16x2 %0, %1;" : "=r"(r) : "r"(x));
    return r;
}
__device__ __forceinline__ uint32_t h2(float x, float y) {
    __half2 t = __floats2half2_rn(x, y);
    return *reinterpret_cast<uint32_t*>(&t);
}

__global__ void __launch_bounds__(256, 2)
swa_mma_kernel(const float* __restrict__ Qg,
               const float* __restrict__ Kg,
               const float* __restrict__ Vg,
               float* __restrict__ Og)
{
    extern __shared__ char smem[];
    const uint32_t sb = smem_u32(smem);

    const int tid  = threadIdx.x;
    const int lane = tid & 31;
    const int w    = tid >> 5;
    const int q0   = blockIdx.x * 32;
    const int kvh  = blockIdx.y;
    const int b    = blockIdx.z;

    const int g  = lane >> 2, tg = lane & 3;
    const int m0 = w * 16 + g, m1 = m0 + 8;

    // ---- Q A-fragments straight from global (scale*log2e folded in) ----
    const float* qrow0 = Qg + ((size_t)(b * SEQ + q0 + (m0 >> 2)) * 32 + kvh * 4 + (m0 & 3)) * 64;
    const float* qrow1 = Qg + ((size_t)(b * SEQ + q0 + (m1 >> 2)) * 32 + kvh * 4 + (m1 & 3)) * 64;
    uint32_t qh[4][4];
#pragma unroll
    for (int kk = 0; kk < 4; ++kk) {
        const int c0 = 16 * kk + 2 * tg;
        const float2 x0 = *reinterpret_cast<const float2*>(qrow0 + c0);
        const float2 x1 = *reinterpret_cast<const float2*>(qrow1 + c0);
        const float2 x2 = *reinterpret_cast<const float2*>(qrow0 + c0 + 8);
        const float2 x3 = *reinterpret_cast<const float2*>(qrow1 + c0 + 8);
        qh[kk][0] = h2(x0.x * SSCALE, x0.y * SSCALE);
        qh[kk][1] = h2(x1.x * SSCALE, x1.y * SSCALE);
        qh[kk][2] = h2(x2.x * SSCALE, x2.y * SSCALE);
        qh[kk][3] = h2(x3.x * SSCALE, x3.y * SSCALE);
    }

    // ---- stage K and V as fp16 (160 key rows: q0-128 .. q0+31) ----
    for (int i = tid; i < 160 * 16; i += 256) {
        const int r = i >> 4, c4 = i & 15;
        const int key = q0 - 128 + r;
        float4 kv = make_float4(0.f, 0.f, 0.f, 0.f), vv = kv;
        if (key >= 0) {
            const size_t gidx = ((size_t)(b * SEQ + key) * 8 + kvh) * 64 + c4 * 4;
            kv = *reinterpret_cast<const float4*>(Kg + gidx);
            vv = *reinterpret_cast<const float4*>(Vg + gidx);
        }
        const uint32_t off = r * 128 + ((((c4 >> 1) ^ (r & 7))) << 4) + ((c4 & 1) << 3);
        *reinterpret_cast<uint2*>(smem + SM_KH + off) = make_uint2(h2(kv.x, kv.y), h2(kv.z, kv.w));
        *reinterpret_cast<uint2*>(smem + SM_VH + off) = make_uint2(h2(vv.x, vv.y), h2(vv.z, vv.w));
    }
    __syncthreads();

    const int jlo0 = max((m0 >> 2) + 1, 128 - q0), jhi0 = (m0 >> 2) + 128;
    const int jlo1 = max((m1 >> 2) + 1, 128 - q0), jhi1 = (m1 >> 2) + 128;

    // hoisted LDSM base addresses (swizzle selector is chunk-invariant)
    const int krow   = (lane & 7) + ((lane & 16) ? 8 : 0);
    const int kchoff = (lane & 8) ? 1 : 0;
    const int vrow   = (lane & 7) + ((lane & 8) ? 8 : 0);
    const int vchof  = (lane & 16) ? 1 : 0;
    uint32_t akk[4], avn[4];
#pragma unroll
    for (int kk = 0; kk < 4; ++kk)
        akk[kk] = sb + SM_KH + krow * 128 + ((uint32_t)((kk * 2 + kchoff) ^ (krow & 7)) << 4);
#pragma unroll
    for (int np = 0; np < 4; ++np)
        avn[np] = sb + SM_VH + vrow * 128 + ((uint32_t)((np * 2 + vchof) ^ (vrow & 7)) << 4);

    float o[8][4];
#pragma unroll
    for (int nt = 0; nt < 8; ++nt)
#pragma unroll
        for (int e = 0; e < 4; ++e) o[nt][e] = 0.f;
    float osum[4] = {0.f, 0.f, 0.f, 0.f};

    // ---- QK for chunk c into s (16 MMAs, 8 LDSM) ----
    auto QK = [&](int c, float (&s)[4][4]) {
        const uint32_t coff = (uint32_t)c * 4096;
#pragma unroll
        for (int t = 0; t < 4; ++t)
#pragma unroll
            for (int e = 0; e < 4; ++e) s[t][e] = 0.f;
#pragma unroll
        for (int kk = 0; kk < 4; ++kk) {
            uint32_t k0[4], k1[4];
            ldsm4(k0, akk[kk] + coff);
            ldsm4(k1, akk[kk] + coff + 2048);
            mma16816(s[0], qh[kk], k0[0], k0[1]);
            mma16816(s[1], qh[kk], k0[2], k0[3]);
            mma16816(s[2], qh[kk], k1[0], k1[1]);
            mma16816(s[3], qh[kk], k1[2], k1[3]);
        }
    };

    // ---- exp + PV for chunk c from s (per 16-key half: 4 LDSM, 9 MMAs) ----
    auto PV = [&](int c, float (&s)[4][4]) {
        const uint32_t coff = (uint32_t)c * 4096;
#pragma unroll
        for (int kk = 0; kk < 2; ++kk) {
            uint32_t vh[4][4];
            ldsm4t(vh[0], avn[0] + coff + (uint32_t)kk * 2048);
            ldsm4t(vh[1], avn[1] + coff + (uint32_t)kk * 2048);
            ldsm4t(vh[2], avn[2] + coff + (uint32_t)kk * 2048);
            ldsm4t(vh[3], avn[3] + coff + (uint32_t)kk * 2048);

            const int jb = 32 * c + 16 * kk + 2 * tg;
            const int j0 = jb,     j1 = jb + 1;
            const int j2 = jb + 8, j3 = jb + 9;
            const float* s0 = s[2 * kk];
            const float* s1 = s[2 * kk + 1];
            const float t00 = (j0 >= jlo0 && j0 <= jhi0) ? s0[0] : -1e30f;
            const float t01 = (j1 >= jlo0 && j1 <= jhi0) ? s0[1] : -1e30f;
            const float t10 = (j0 >= jlo1 && j0 <= jhi1) ? s0[2] : -1e30f;
            const float t11 = (j1 >= jlo1 && j1 <= jhi1) ? s0[3] : -1e30f;
            const float t02 = (j2 >= jlo0 && j2 <= jhi0) ? s1[0] : -1e30f;
            const float t03 = (j3 >= jlo0 && j3 <= jhi0) ? s1[1] : -1e30f;
            const float t12 = (j2 >= jlo1 && j2 <= jhi1) ? s1[2] : -1e30f;
            const float t13 = (j3 >= jlo1 && j3 <= jhi1) ? s1[3] : -1e30f;
            uint32_t phi[4];
            phi[0] = ex2h2(cvt2h(t00, t01));   // -1e30 -> -inf -> 2^-inf = 0
            phi[1] = ex2h2(cvt2h(t10, t11));
            phi[2] = ex2h2(cvt2h(t02, t03));
            phi[3] = ex2h2(cvt2h(t12, t13));

            mma16816(o[0], phi, vh[0][0], vh[0][1]);
            mma16816(o[1], phi, vh[0][2], vh[0][3]);
            mma16816(o[2], phi, vh[1][0], vh[1][1]);
            mma16816(o[3], phi, vh[1][2], vh[1][3]);
            mma16816(o[4], phi, vh[2][0], vh[2][1]);
            mma16816(o[5], phi, vh[2][2], vh[2][3]);
            mma16816(o[6], phi, vh[3][0], vh[3][1]);
            mma16816(o[7], phi, vh[3][2], vh[3][3]);
            mma16816(osum, phi, ONES2, ONES2);
        }
    };

    // ---- software-pipelined chunk schedule (chunks are independent) ----
    float sA[4][4], sB[4][4];
    if (q0 == 0) {
        // keys 0..127 fully masked for the first block: only chunk 4 is live
        QK(4, sA);
        PV(4, sA);
    } else {
        QK(0, sA);
        QK(1, sB); PV(0, sA);
        QK(2, sA); PV(1, sB);
        QK(3, sB); PV(2, sA);
        QK(4, sA); PV(3, sB);
        PV(4, sA);
    }

    // ================= normalize + store (O layout == Q layout) =================
    const float inv0 = 1.f / osum[0], inv1 = 1.f / osum[2];
    float* ob0 = Og + (qrow0 - Qg);
    float* ob1 = Og + (qrow1 - Qg);
#pragma unroll
    for (int nt = 0; nt < 8; ++nt) {
        const int d = nt * 8 + 2 * tg;
        *reinterpret_cast<float2*>(ob0 + d) = make_float2(o[nt][0] * inv0, o[nt][1] * inv0);
        *reinterpret_cast<float2*>(ob1 + d) = make_float2(o[nt][2] * inv1, o[nt][3] * inv1);
    }
}

} // namespace

extern "C" void kernel_launch(void* const* d_in, const int* in_sizes, int n_in,
                              void* d_out, int out_size)
{
    (void)in_sizes; (void)n_in; (void)out_size;
    const float* Q = (const float*)d_in[0];
    const float* K = (const float*)d_in[1];
    const float* V = (const float*)d_in[2];
    // d_in[3] = sinks — unused by the reference math, faithfully ignored.
    float* O = (float*)d_out;

    cudaFuncSetAttribute(swa_mma_kernel, cudaFuncAttributeMaxDynamicSharedMemorySize,
                         SMEM_BYTES);

    dim3 grid(SEQ / 32, 8, 2);
    swa_mma_kernel<<<grid, 256, SMEM_BYTES>>>(Q, K, V, O);
}

// round 16
// speedup vs baseline: 1.0589x; 1.0589x over previous
#include <cuda_runtime.h>
#include <cuda_fp16.h>
#include <cstdint>
#include <math.h>

// Sliding-window causal GQA attention via mma.sync (HMMA), fp16 operands.
// B=2, S=2048, 8 kv heads x 4 q-heads/kv, D=64, WINDOW=128, fp32 in/out.
// CTA = (b, kvh, 64 queries): ONE 192-row K/V window staged (48KB smem,
// 2 CTAs/SM), then two 32-query blocks computed back-to-back over it
// (block B = same code at +32-row offset). Amortizes the global-latency
// prologue and cuts staged K/V traffic per query by 40%.
// Per block: M=128 rows (32q x 4h), 8 warps, keys in 5 chunks of 32.
// Shuffle-free softmax: p = 2^s (offset-invariant, fp16-safe range) via
// ex2.approx.f16x2; row-sum via ones-column MMA. rel_err ~5.7e-4.

namespace {

constexpr int SEQ = 2048;
constexpr float SSCALE = 0.125f * 1.4426950408889634f;  // 1/sqrt(64) * log2(e)
constexpr uint32_t ONES2 = 0x3C003C00u;                  // half2(1, 1)

constexpr int SM_KH = 0;           // 192 x 128B
constexpr int SM_VH = 24576;
constexpr int SMEM_BYTES = 49152;  // 48 KB -> 2 CTAs/SM

__device__ __forceinline__ uint32_t smem_u32(const void* p) {
    uint32_t a;
    asm("{ .reg .u64 t; cvta.to.shared.u64 t, %1; cvt.u32.u64 %0, t; }" : "=r"(a) : "l"(p));
    return a;
}
__device__ __forceinline__ void ldsm4(uint32_t r[4], uint32_t a) {
    asm volatile("ldmatrix.sync.aligned.m8n8.x4.shared.b16 {%0,%1,%2,%3}, [%4];"
                 : "=r"(r[0]), "=r"(r[1]), "=r"(r[2]), "=r"(r[3]) : "r"(a));
}
__device__ __forceinline__ void ldsm4t(uint32_t r[4], uint32_t a) {
    asm volatile("ldmatrix.sync.aligned.m8n8.x4.trans.shared.b16 {%0,%1,%2,%3}, [%4];"
                 : "=r"(r[0]), "=r"(r[1]), "=r"(r[2]), "=r"(r[3]) : "r"(a));
}
__device__ __forceinline__ void mma16816(float d[4], const uint32_t a[4],
                                         uint32_t b0, uint32_t b1) {
    asm("mma.sync.aligned.m16n8k16.row.col.f32.f16.f16.f32 "
        "{%0,%1,%2,%3}, {%4,%5,%6,%7}, {%8,%9}, {%0,%1,%2,%3};"
        : "+f"(d[0]), "+f"(d[1]), "+f"(d[2]), "+f"(d[3])
        : "r"(a[0]), "r"(a[1]), "r"(a[2]), "r"(a[3]), "r"(b0), "r"(b1));
}
__device__ __forceinline__ uint32_t cvt2h(float lo, float hi) {
    uint32_t r; asm("cvt.rn.f16x2.f32 %0, %2, %1;" : "=r"(r) : "f"(lo), "f"(hi));
    return r;
}
__device__ __forceinline__ uint32_t ex2h2(uint32_t x) {
    uint32_t r; asm("ex2.approx.f16x2 %0, %1;" : "=r"(r) : "r"(x));
    return r;
}
__device__ __forceinline__ uint32_t h2(float x, float y) {
    __half2 t = __floats2half2_rn(x, y);
    return *reinterpret_cast<uint32_t*>(&t);
}

__global__ void __launch_bounds__(256, 2)
swa_mma_kernel(const float* __restrict__ Qg,
               const float* __restrict__ Kg,
               const float* __restrict__ Vg,
               float* __restrict__ Og)
{
    extern __shared__ char smem[];
    const uint32_t sb = smem_u32(smem);

    const int tid  = threadIdx.x;
    const int lane = tid & 31;
    const int w    = tid >> 5;
    const int q0   = blockIdx.x * 64;
    const int kvh  = blockIdx.y;
    const int b    = blockIdx.z;

    const int g  = lane >> 2, tg = lane & 3;

    // ---- stage K and V as fp16 (192 key rows: q0-128 .. q0+63) ----
    for (int i = tid; i < 192 * 16; i += 256) {
        const int r = i >> 4, c4 = i & 15;
        const int key = q0 - 128 + r;
        float4 kv = make_float4(0.f, 0.f, 0.f, 0.f), vv = kv;
        if (key >= 0) {
            const size_t gidx = ((size_t)(b * SEQ + key) * 8 + kvh) * 64 + c4 * 4;
            kv = *reinterpret_cast<const float4*>(Kg + gidx);
            vv = *reinterpret_cast<const float4*>(Vg + gidx);
        }
        const uint32_t off = r * 128 + ((((c4 >> 1) ^ (r & 7))) << 4) + ((c4 & 1) << 3);
        *reinterpret_cast<uint2*>(smem + SM_KH + off) = make_uint2(h2(kv.x, kv.y), h2(kv.z, kv.w));
        *reinterpret_cast<uint2*>(smem + SM_VH + off) = make_uint2(h2(vv.x, vv.y), h2(vv.z, vv.w));
    }
    __syncthreads();

    // hoisted LDSM base addresses (swizzle selector is row-offset invariant:
    // block/chunk offsets are multiples of 32 rows, so row&7 is fixed)
    const int krow   = (lane & 7) + ((lane & 16) ? 8 : 0);
    const int kchoff = (lane & 8) ? 1 : 0;
    const int vrow   = (lane & 7) + ((lane & 8) ? 8 : 0);
    const int vchof  = (lane & 16) ? 1 : 0;
    uint32_t akk[4], avn[4];
#pragma unroll
    for (int kk = 0; kk < 4; ++kk)
        akk[kk] = sb + SM_KH + krow * 128 + ((uint32_t)((kk * 2 + kchoff) ^ (krow & 7)) << 4);
#pragma unroll
    for (int np = 0; np < 4; ++np)
        avn[np] = sb + SM_VH + vrow * 128 + ((uint32_t)((np * 2 + vchof) ^ (vrow & 7)) << 4);

    // ================= one 32-query block over window rows base.. =============
    auto run_block = [&](int qb, uint32_t base, int cstart) {
        const int m0 = w * 16 + g, m1 = m0 + 8;
        const float* qrow0 =
            Qg + ((size_t)(b * SEQ + qb + (m0 >> 2)) * 32 + kvh * 4 + (m0 & 3)) * 64;
        const float* qrow1 =
            Qg + ((size_t)(b * SEQ + qb + (m1 >> 2)) * 32 + kvh * 4 + (m1 & 3)) * 64;

        // Q A-fragments straight from global (scale*log2e folded in)
        uint32_t qh[4][4];
#pragma unroll
        for (int kk = 0; kk < 4; ++kk) {
            const int c0 = 16 * kk + 2 * tg;
            const float2 x0 = *reinterpret_cast<const float2*>(qrow0 + c0);
            const float2 x1 = *reinterpret_cast<const float2*>(qrow1 + c0);
            const float2 x2 = *reinterpret_cast<const float2*>(qrow0 + c0 + 8);
            const float2 x3 = *reinterpret_cast<const float2*>(qrow1 + c0 + 8);
            qh[kk][0] = h2(x0.x * SSCALE, x0.y * SSCALE);
            qh[kk][1] = h2(x1.x * SSCALE, x1.y * SSCALE);
            qh[kk][2] = h2(x2.x * SSCALE, x2.y * SSCALE);
            qh[kk][3] = h2(x3.x * SSCALE, x3.y * SSCALE);
        }

        const int jlo0 = max((m0 >> 2) + 1, 128 - qb), jhi0 = (m0 >> 2) + 128;
        const int jlo1 = max((m1 >> 2) + 1, 128 - qb), jhi1 = (m1 >> 2) + 128;

        float o[8][4];
#pragma unroll
        for (int nt = 0; nt < 8; ++nt)
#pragma unroll
            for (int e = 0; e < 4; ++e) o[nt][e] = 0.f;
        float osum[4] = {0.f, 0.f, 0.f, 0.f};

#pragma unroll 1
        for (int c = cstart; c < 5; ++c) {
            const uint32_t coff = base + (uint32_t)c * 4096;

            // ---------- QK chunk: S[16,32] (S pre-scaled via Q) ----------
            float s[4][4];
#pragma unroll
            for (int t = 0; t < 4; ++t)
#pragma unroll
                for (int e = 0; e < 4; ++e) s[t][e] = 0.f;
#pragma unroll
            for (int kk = 0; kk < 4; ++kk) {
                uint32_t k0[4], k1[4];
                ldsm4(k0, akk[kk] + coff);
                ldsm4(k1, akk[kk] + coff + 2048);
                mma16816(s[0], qh[kk], k0[0], k0[1]);
                mma16816(s[1], qh[kk], k0[2], k0[3]);
                mma16816(s[2], qh[kk], k1[0], k1[1]);
                mma16816(s[3], qh[kk], k1[2], k1[3]);
            }

            // ---- per-16-key half: prefetch V, exp+pack, MMA ----
#pragma unroll
            for (int kk = 0; kk < 2; ++kk) {
                uint32_t vh[4][4];
                ldsm4t(vh[0], avn[0] + coff + (uint32_t)kk * 2048);
                ldsm4t(vh[1], avn[1] + coff + (uint32_t)kk * 2048);
                ldsm4t(vh[2], avn[2] + coff + (uint32_t)kk * 2048);
                ldsm4t(vh[3], avn[3] + coff + (uint32_t)kk * 2048);

                const int jb = 32 * c + 16 * kk + 2 * tg;
                const int j0 = jb,     j1 = jb + 1;
                const int j2 = jb + 8, j3 = jb + 9;
                const float* s0 = s[2 * kk];
                const float* s1 = s[2 * kk + 1];
                const float t00 = (j0 >= jlo0 && j0 <= jhi0) ? s0[0] : -1e30f;
                const float t01 = (j1 >= jlo0 && j1 <= jhi0) ? s0[1] : -1e30f;
                const float t10 = (j0 >= jlo1 && j0 <= jhi1) ? s0[2] : -1e30f;
                const float t11 = (j1 >= jlo1 && j1 <= jhi1) ? s0[3] : -1e30f;
                const float t02 = (j2 >= jlo0 && j2 <= jhi0) ? s1[0] : -1e30f;
                const float t03 = (j3 >= jlo0 && j3 <= jhi0) ? s1[1] : -1e30f;
                const float t12 = (j2 >= jlo1 && j2 <= jhi1) ? s1[2] : -1e30f;
                const float t13 = (j3 >= jlo1 && j3 <= jhi1) ? s1[3] : -1e30f;
                uint32_t phi[4];
                phi[0] = ex2h2(cvt2h(t00, t01));   // -1e30 -> -inf -> 2^-inf = 0
                phi[1] = ex2h2(cvt2h(t10, t11));
                phi[2] = ex2h2(cvt2h(t02, t03));
                phi[3] = ex2h2(cvt2h(t12, t13));

                mma16816(o[0], phi, vh[0][0], vh[0][1]);
                mma16816(o[1], phi, vh[0][2], vh[0][3]);
                mma16816(o[2], phi, vh[1][0], vh[1][1]);
                mma16816(o[3], phi, vh[1][2], vh[1][3]);
                mma16816(o[4], phi, vh[2][0], vh[2][1]);
                mma16816(o[5], phi, vh[2][2], vh[2][3]);
                mma16816(o[6], phi, vh[3][0], vh[3][1]);
                mma16816(o[7], phi, vh[3][2], vh[3][3]);
                mma16816(osum, phi, ONES2, ONES2);   // row-sum, quad-replicated
            }
        }

        // ---- normalize + store (O layout == Q layout) ----
        const float inv0 = 1.f / osum[0], inv1 = 1.f / osum[2];
        float* ob0 = Og + (qrow0 - Qg);
        float* ob1 = Og + (qrow1 - Qg);
#pragma unroll
        for (int nt = 0; nt < 8; ++nt) {
            const int d = nt * 8 + 2 * tg;
            *reinterpret_cast<float2*>(ob0 + d) = make_float2(o[nt][0] * inv0, o[nt][1] * inv0);
            *reinterpret_cast<float2*>(ob1 + d) = make_float2(o[nt][2] * inv1, o[nt][3] * inv1);
        }
    };

    // Block A: queries q0..q0+31 over rows 0..159; block B: +32 queries/rows.
    // q0 == 0: A has only chunk 4 live (keys 0..31); B chunks 3,4 (keys 0..63).
    run_block(q0,      0u,    (q0 == 0) ? 4 : 0);
    run_block(q0 + 32, 4096u, (q0 == 0) ? 3 : 0);
}

} // namespace

extern "C" void kernel_launch(void* const* d_in, const int* in_sizes, int n_in,
                              void* d_out, int out_size)
{
    (void)in_sizes; (void)n_in; (void)out_size;
    const float* Q = (const float*)d_in[0];
    const float* K = (const float*)d_in[1];
    const float* V = (const float*)d_in[2];
    // d_in[3] = sinks — unused by the reference math, faithfully ignored.
    float* O = (float*)d_out;

    cudaFuncSetAttribute(swa_mma_kernel, cudaFuncAttributeMaxDynamicSharedMemorySize,
                         SMEM_BYTES);

    dim3 grid(SEQ / 64, 8, 2);
    swa_mma_kernel<<<grid, 256, SMEM_BYTES>>>(Q, K, V, O);
}